// round 5
// baseline (speedup 1.0000x reference)
#include <cuda_runtime.h>
#include <math.h>

// Problem dims (fixed by setup_inputs)
#define BQ   256
#define DD   1024
#define NMEM 100000
#define KTOP 16

// Output layout (float32, concatenated in reference-return order)
#define OFF_REF  0
#define OFF_VALS (BQ * DD)                  // 262144
#define OFF_IDX  (OFF_VALS + BQ * KTOP)     // 266240
#define OFF_RET  (OFF_IDX + BQ * KTOP)      // 270336

// ---------------- scratch (__device__ globals; no allocs) ----------------
__device__ float g_h[BQ * DD];
__device__ float g_t[BQ * DD];
__device__ float g_refined[BQ * DD];
__device__ float g_rnorm[NMEM];
__device__ float g_sims[(size_t)BQ * NMEM];   // ~102.4 MB
__device__ int   g_tidx[BQ * KTOP];

// ---------------- block reduction helper ----------------
__device__ __forceinline__ float block_sum(float v, float* red) {
    int t = threadIdx.x;
    #pragma unroll
    for (int o = 16; o > 0; o >>= 1) v += __shfl_xor_sync(0xffffffffu, v, o);
    __syncthreads();
    if ((t & 31) == 0) red[t >> 5] = v;
    __syncthreads();
    if (t == 0) {
        float s = red[0];
        int nw = blockDim.x >> 5;
        for (int w = 1; w < nw; ++w) s += red[w];
        red[0] = s;
    }
    __syncthreads();
    return red[0];
}

// ---------------- NT GEMM: C[M,N] = A[M,K] * B[N,K]^T ----------------
// BM=128 BN=128 BK=16, 256 threads, 8x8 per-thread tile, double-buffered smem.
// Requires: M % 128 == 0, K % 16 == 0, N % 8 == 0 (N edge handled by guards).
// Optional bias[n] add and scale[n] multiply in epilogue.
// streamC != 0 -> use streaming (evict-first) stores for C.
#define BM 128
#define BN 128
#define BK 16

__global__ __launch_bounds__(256, 2)
void gemm_nt(const float* __restrict__ A, const float* __restrict__ B,
             const float* __restrict__ bias, const float* __restrict__ scale,
             float* __restrict__ C, int M, int N, int K, int streamC)
{
    __shared__ float As[2][BK][BM];
    __shared__ float Bs[2][BK][BN];

    const int t   = threadIdx.x;
    const int tx  = t & 15;            // 16 thread cols, TN=8
    const int ty  = t >> 4;            // 16 thread rows, TM=8
    const int m0  = blockIdx.y * BM;
    const int n0  = blockIdx.x * BN;

    // global load mapping: 128 rows x 4 k-segments = 512 float4 per operand;
    // each thread loads float4 #t and #(t+256).
    int lr[2], ls[2];
    #pragma unroll
    for (int l = 0; l < 2; ++l) {
        int idx = t + l * 256;
        lr[l] = idx >> 2;              // row 0..127
        ls[l] = (idx & 3) * 4;         // k-offset 0,4,8,12
    }
    const float* gA0 = A + (size_t)(m0 + lr[0]) * K + ls[0];
    const float* gA1 = A + (size_t)(m0 + lr[1]) * K + ls[1];
    const int    br0 = n0 + lr[0];
    const int    br1 = n0 + lr[1];
    const float* gB0 = B + (size_t)br0 * K + ls[0];
    const float* gB1 = B + (size_t)br1 * K + ls[1];
    const bool   bv0 = (br0 < N);
    const bool   bv1 = (br1 < N);

    float acc[8][8];
    #pragma unroll
    for (int i = 0; i < 8; ++i)
        #pragma unroll
        for (int j = 0; j < 8; ++j) acc[i][j] = 0.f;

    float4 avr[2], bvr[2];
    avr[0] = *(const float4*)(gA0);
    avr[1] = *(const float4*)(gA1);
    bvr[0] = bv0 ? *(const float4*)(gB0) : make_float4(0.f, 0.f, 0.f, 0.f);
    bvr[1] = bv1 ? *(const float4*)(gB1) : make_float4(0.f, 0.f, 0.f, 0.f);

    // store tile 0
    #pragma unroll
    for (int l = 0; l < 2; ++l) {
        As[0][ls[l] + 0][lr[l]] = avr[l].x;
        As[0][ls[l] + 1][lr[l]] = avr[l].y;
        As[0][ls[l] + 2][lr[l]] = avr[l].z;
        As[0][ls[l] + 3][lr[l]] = avr[l].w;
        Bs[0][ls[l] + 0][lr[l]] = bvr[l].x;
        Bs[0][ls[l] + 1][lr[l]] = bvr[l].y;
        Bs[0][ls[l] + 2][lr[l]] = bvr[l].z;
        Bs[0][ls[l] + 3][lr[l]] = bvr[l].w;
    }
    __syncthreads();

    int buf = 0;
    for (int k0 = 0; k0 < K; k0 += BK) {
        const bool more = (k0 + BK) < K;
        // prefetch next tiles to registers (overlaps with FMA loop below)
        if (more) {
            avr[0] = *(const float4*)(gA0 + k0 + BK);
            avr[1] = *(const float4*)(gA1 + k0 + BK);
            bvr[0] = bv0 ? *(const float4*)(gB0 + k0 + BK) : make_float4(0.f, 0.f, 0.f, 0.f);
            bvr[1] = bv1 ? *(const float4*)(gB1 + k0 + BK) : make_float4(0.f, 0.f, 0.f, 0.f);
        }

        #pragma unroll
        for (int kk = 0; kk < BK; ++kk) {
            float4 a0 = *(const float4*)&As[buf][kk][ty * 8 + 0];
            float4 a1 = *(const float4*)&As[buf][kk][ty * 8 + 4];
            float4 b0 = *(const float4*)&Bs[buf][kk][tx * 8 + 0];
            float4 b1 = *(const float4*)&Bs[buf][kk][tx * 8 + 4];
            float a[8] = {a0.x, a0.y, a0.z, a0.w, a1.x, a1.y, a1.z, a1.w};
            float b[8] = {b0.x, b0.y, b0.z, b0.w, b1.x, b1.y, b1.z, b1.w};
            #pragma unroll
            for (int i = 0; i < 8; ++i)
                #pragma unroll
                for (int j = 0; j < 8; ++j)
                    acc[i][j] = fmaf(a[i], b[j], acc[i][j]);
        }

        if (more) {
            int nb = buf ^ 1;
            #pragma unroll
            for (int l = 0; l < 2; ++l) {
                As[nb][ls[l] + 0][lr[l]] = avr[l].x;
                As[nb][ls[l] + 1][lr[l]] = avr[l].y;
                As[nb][ls[l] + 2][lr[l]] = avr[l].z;
                As[nb][ls[l] + 3][lr[l]] = avr[l].w;
                Bs[nb][ls[l] + 0][lr[l]] = bvr[l].x;
                Bs[nb][ls[l] + 1][lr[l]] = bvr[l].y;
                Bs[nb][ls[l] + 2][lr[l]] = bvr[l].z;
                Bs[nb][ls[l] + 3][lr[l]] = bvr[l].w;
            }
            __syncthreads();
            buf = nb;
        }
    }

    // epilogue: two guarded float4 stores per row (N is a multiple of 8 here)
    const int nbase = n0 + tx * 8;
    if (nbase < N) {
        float bb[8], sc[8];
        #pragma unroll
        for (int j = 0; j < 8; ++j) { bb[j] = 0.f; sc[j] = 1.f; }
        if (bias) {
            #pragma unroll
            for (int j = 0; j < 8; ++j) bb[j] = bias[nbase + j];
        }
        if (scale) {
            #pragma unroll
            for (int j = 0; j < 8; ++j) sc[j] = scale[nbase + j];
        }
        #pragma unroll
        for (int i = 0; i < 8; ++i) {
            int m = m0 + ty * 8 + i;
            float4 v0, v1;
            v0.x = (acc[i][0] + bb[0]) * sc[0];
            v0.y = (acc[i][1] + bb[1]) * sc[1];
            v0.z = (acc[i][2] + bb[2]) * sc[2];
            v0.w = (acc[i][3] + bb[3]) * sc[3];
            v1.x = (acc[i][4] + bb[4]) * sc[4];
            v1.y = (acc[i][5] + bb[5]) * sc[5];
            v1.z = (acc[i][6] + bb[6]) * sc[6];
            v1.w = (acc[i][7] + bb[7]) * sc[7];
            float4* c0 = (float4*)(C + (size_t)m * N + nbase);
            float4* c1 = (float4*)(C + (size_t)m * N + nbase + 4);
            if (streamC) {
                __stcs(c0, v0);        // st.global.cs: evict-first, C is consumed once
                __stcs(c1, v1);
            } else {
                *c0 = v0;
                *c1 = v1;
            }
        }
    }
}

// ---------------- LayerNorm + exact GELU (in-place), one block per row ----------------
__global__ __launch_bounds__(256)
void ln_gelu_kernel(float* __restrict__ h, const float* __restrict__ g,
                    const float* __restrict__ b)
{
    __shared__ float red[8];
    int row = blockIdx.x, t = threadIdx.x;
    float4 x = *(const float4*)(h + (size_t)row * DD + t * 4);

    float s = x.x + x.y + x.z + x.w;
    s = block_sum(s, red);
    float mean = s * (1.0f / DD);

    float dx = x.x - mean, dy = x.y - mean, dz = x.z - mean, dw = x.w - mean;
    float ss = dx * dx + dy * dy + dz * dz + dw * dw;
    ss = block_sum(ss, red);
    float rstd = rsqrtf(ss * (1.0f / DD) + 1e-5f);

    float4 gg = *(const float4*)(g + t * 4);
    float4 bb = *(const float4*)(b + t * 4);
    float y0 = dx * rstd * gg.x + bb.x;
    float y1 = dy * rstd * gg.y + bb.y;
    float y2 = dz * rstd * gg.z + bb.z;
    float y3 = dw * rstd * gg.w + bb.w;

    const float inv_sqrt2 = 0.70710678118654752f;
    float4 o;
    o.x = y0 * 0.5f * (1.0f + erff(y0 * inv_sqrt2));
    o.y = y1 * 0.5f * (1.0f + erff(y1 * inv_sqrt2));
    o.z = y2 * 0.5f * (1.0f + erff(y2 * inv_sqrt2));
    o.w = y3 * 0.5f * (1.0f + erff(y3 * inv_sqrt2));
    *(float4*)(h + (size_t)row * DD + t * 4) = o;
}

// ---------------- row L2 normalize: writes scratch + d_out refined region ----------------
__global__ __launch_bounds__(256)
void l2norm_rows_kernel(const float* __restrict__ in, float* __restrict__ out_scratch,
                        float* __restrict__ out_final)
{
    __shared__ float red[8];
    int row = blockIdx.x, t = threadIdx.x;
    float4 x = *(const float4*)(in + (size_t)row * DD + t * 4);
    float ss = x.x * x.x + x.y * x.y + x.z * x.z + x.w * x.w;
    ss = block_sum(ss, red);
    float inv = 1.0f / fmaxf(sqrtf(ss), 1e-12f);
    float4 o = make_float4(x.x * inv, x.y * inv, x.z * inv, x.w * inv);
    *(float4*)(out_scratch + (size_t)row * DD + t * 4) = o;
    *(float4*)(out_final + OFF_REF + (size_t)row * DD + t * 4) = o;
}

// ---------------- memory row inverse norms ----------------
__global__ __launch_bounds__(128)
void rnorm_kernel(const float* __restrict__ mem)
{
    __shared__ float red[4];
    int row = blockIdx.x, t = threadIdx.x;
    const float* p = mem + (size_t)row * DD;
    float4 a = *(const float4*)(p + t * 8);
    float4 c = *(const float4*)(p + t * 8 + 4);
    float ss = a.x*a.x + a.y*a.y + a.z*a.z + a.w*a.w
             + c.x*c.x + c.y*c.y + c.z*c.z + c.w*c.w;
    ss = block_sum(ss, red);
    if (t == 0) g_rnorm[row] = 1.0f / fmaxf(sqrtf(ss), 1e-12f);
}

// ---------------- top-k (k=16) per row, one block per row ----------------
// Tie-break matches jax.lax.top_k: equal values -> smaller index first.
__device__ __forceinline__ bool lexgt(float v2, int i2, float v1, int i1) {
    return (v2 > v1) || (v2 == v1 && i2 < i1);
}

__device__ __forceinline__ void topk_insert(float v, int i, float* val, int* idx) {
    if (lexgt(v, i, val[KTOP - 1], idx[KTOP - 1])) {
        float cv = v; int ci = i;
        #pragma unroll
        for (int j = 0; j < KTOP; ++j) {
            if (lexgt(cv, ci, val[j], idx[j])) {
                float tv = val[j]; int ti = idx[j];
                val[j] = cv; idx[j] = ci;
                cv = tv; ci = ti;
            }
        }
    }
}

__global__ __launch_bounds__(256)
void topk_kernel(const float* __restrict__ sims, float* __restrict__ out)
{
    __shared__ float s_val[256 * KTOP];
    __shared__ int   s_idx[256 * KTOP];
    __shared__ float s_wv[8];
    __shared__ int   s_wi[8];
    __shared__ int   s_fi;

    int row = blockIdx.x, t = threadIdx.x;
    const float4* p4 = (const float4*)(sims + (size_t)row * NMEM);

    float val[KTOP];
    int   idx[KTOP];
    #pragma unroll
    for (int j = 0; j < KTOP; ++j) { val[j] = -INFINITY; idx[j] = 0x7fffffff; }

    // NMEM % 8 == 0; scan with 2x float4 streaming loads per iteration
    // (MLP=2/thread). Ascending-index insertion preserves jax's tie-break.
    const int nq = NMEM / 4;            // 25000
    for (int q = t * 2; q < nq; q += 512) {
        float4 u4 = __ldcs(p4 + q);
        float4 w4 = __ldcs(p4 + q + 1);
        int base = q * 4;
        float e[8] = {u4.x, u4.y, u4.z, u4.w, w4.x, w4.y, w4.z, w4.w};
        #pragma unroll
        for (int s = 0; s < 8; ++s)
            topk_insert(e[s], base + s, val, idx);
    }
    #pragma unroll
    for (int j = 0; j < KTOP; ++j) { s_val[t * KTOP + j] = val[j]; s_idx[t * KTOP + j] = idx[j]; }
    __syncthreads();

    for (int r = 0; r < KTOP; ++r) {
        float bv = -INFINITY; int bi = 0x7fffffff;
        #pragma unroll
        for (int j = 0; j < KTOP; ++j) {
            float v = s_val[t * KTOP + j]; int i = s_idx[t * KTOP + j];
            if (lexgt(v, i, bv, bi)) { bv = v; bi = i; }
        }
        #pragma unroll
        for (int o = 16; o > 0; o >>= 1) {
            float ov = __shfl_down_sync(0xffffffffu, bv, o);
            int   oi = __shfl_down_sync(0xffffffffu, bi, o);
            if (lexgt(ov, oi, bv, bi)) { bv = ov; bi = oi; }
        }
        if ((t & 31) == 0) { s_wv[t >> 5] = bv; s_wi[t >> 5] = bi; }
        __syncthreads();
        if (t == 0) {
            float fv = s_wv[0]; int fi = s_wi[0];
            for (int w = 1; w < 8; ++w)
                if (lexgt(s_wv[w], s_wi[w], fv, fi)) { fv = s_wv[w]; fi = s_wi[w]; }
            s_fi = fi;
            out[OFF_VALS + row * KTOP + r] = fv;
            out[OFF_IDX  + row * KTOP + r] = (float)fi;
            g_tidx[row * KTOP + r] = fi;
        }
        __syncthreads();
        int fi = s_fi;
        #pragma unroll
        for (int j = 0; j < KTOP; ++j)
            if (s_idx[t * KTOP + j] == fi) s_val[t * KTOP + j] = -INFINITY;
        __syncthreads();
    }
}

// ---------------- gather retrieved = mem_n[idx] ----------------
__global__ __launch_bounds__(256)
void gather_kernel(const float* __restrict__ mem, float* __restrict__ out)
{
    int pair = blockIdx.x;            // 0..BQ*KTOP-1
    int idx  = g_tidx[pair];
    float s  = g_rnorm[idx];
    int t = threadIdx.x;
    float4 v = *(const float4*)(mem + (size_t)idx * DD + t * 4);
    float4 o = make_float4(v.x * s, v.y * s, v.z * s, v.w * s);
    *(float4*)(out + OFF_RET + (size_t)pair * DD + t * 4) = o;
}

// ---------------- launch ----------------
extern "C" void kernel_launch(void* const* d_in, const int* in_sizes, int n_in,
                              void* d_out, int out_size)
{
    const float* query = (const float*)d_in[0];
    const float* W1    = (const float*)d_in[1];
    const float* b1    = (const float*)d_in[2];
    const float* ln_g  = (const float*)d_in[3];
    const float* ln_b  = (const float*)d_in[4];
    const float* W2    = (const float*)d_in[5];
    const float* b2    = (const float*)d_in[6];
    const float* mem   = (const float*)d_in[7];
    float* out = (float*)d_out;

    float *p_h, *p_t, *p_ref, *p_sims, *p_rn;
    cudaGetSymbolAddress((void**)&p_h,    g_h);
    cudaGetSymbolAddress((void**)&p_t,    g_t);
    cudaGetSymbolAddress((void**)&p_ref,  g_refined);
    cudaGetSymbolAddress((void**)&p_sims, g_sims);
    cudaGetSymbolAddress((void**)&p_rn,   g_rnorm);

    // memory row inverse norms (independent; launch early)
    rnorm_kernel<<<NMEM, 128>>>(mem);

    // h = query @ W1^T + b1
    gemm_nt<<<dim3(DD / BN, BQ / BM), 256>>>(query, W1, b1, nullptr, p_h, BQ, DD, DD, 0);
    // LayerNorm + GELU (in place)
    ln_gelu_kernel<<<BQ, 256>>>(p_h, ln_g, ln_b);
    // t = h @ W2^T + b2
    gemm_nt<<<dim3(DD / BN, BQ / BM), 256>>>(p_h, W2, b2, nullptr, p_t, BQ, DD, DD, 0);
    // refined = l2norm(t)  (also writes d_out refined region)
    l2norm_rows_kernel<<<BQ, 256>>>(p_t, p_ref, out);

    // sims[b,n] = dot(refined[b], mem[n]) * rnorm[n]  (streaming C stores)
    gemm_nt<<<dim3((NMEM + BN - 1) / BN, BQ / BM), 256>>>(p_ref, mem, nullptr, p_rn,
                                                          p_sims, BQ, NMEM, DD, 1);
    // top-16 per row (vals + idx, jax tie-break: smaller index first)
    topk_kernel<<<BQ, 256>>>(p_sims, out);
    // retrieved = mem_n[idx]
    gather_kernel<<<BQ * KTOP, 256>>>(mem, out);
}

// round 9
// speedup vs baseline: 1.0970x; 1.0970x over previous
#include <cuda_runtime.h>
#include <math.h>

// Problem dims (fixed by setup_inputs)
#define BQ   256
#define DD   1024
#define NMEM 100000
#define KTOP 16
#define SK   4          // split-K factor for small GEMMs

// Output layout (float32, concatenated in reference-return order)
#define OFF_REF  0
#define OFF_VALS (BQ * DD)                  // 262144
#define OFF_IDX  (OFF_VALS + BQ * KTOP)     // 266240
#define OFF_RET  (OFF_IDX + BQ * KTOP)      // 270336

// ---------------- scratch (__device__ globals; no allocs) ----------------
__device__ float g_h[BQ * DD];
__device__ float g_t[BQ * DD];
__device__ float g_refined[BQ * DD];
__device__ float g_rnorm[NMEM];
__device__ float g_sims[(size_t)BQ * NMEM];   // ~102.4 MB
__device__ float g_part[SK * BQ * DD];        // split-K partials (4 MB)
__device__ int   g_tidx[BQ * KTOP];

// ---------------- f32x2 packed-math helpers ----------------
__device__ __forceinline__ unsigned long long ffma2(unsigned long long a,
                                                    unsigned long long b,
                                                    unsigned long long c) {
    unsigned long long d;
    asm("fma.rn.f32x2 %0, %1, %2, %3;" : "=l"(d) : "l"(a), "l"(b), "l"(c));
    return d;
}
__device__ __forceinline__ unsigned long long pack2(float lo, float hi) {
    unsigned long long r;
    asm("mov.b64 %0, {%1, %2};" : "=l"(r) : "f"(lo), "f"(hi));
    return r;
}
__device__ __forceinline__ void unpack2(unsigned long long v, float& lo, float& hi) {
    asm("mov.b64 {%0, %1}, %2;" : "=f"(lo), "=f"(hi) : "l"(v));
}

// ---------------- block reduction helper ----------------
__device__ __forceinline__ float block_sum(float v, float* red) {
    int t = threadIdx.x;
    #pragma unroll
    for (int o = 16; o > 0; o >>= 1) v += __shfl_xor_sync(0xffffffffu, v, o);
    __syncthreads();
    if ((t & 31) == 0) red[t >> 5] = v;
    __syncthreads();
    if (t == 0) {
        float s = red[0];
        int nw = blockDim.x >> 5;
        for (int w = 1; w < nw; ++w) s += red[w];
        red[0] = s;
    }
    __syncthreads();
    return red[0];
}

// ---------------- sims GEMM: C[M,N] = (A[M,K] * B[N,K]^T) * scale[n] ----------------
// BM=128 BN=128 BK=16, 256 threads, 8x8 per-thread tile, double-buffered smem,
// packed f32x2 FMA inner loop (acc pairs over j). Streaming C stores.
#define BM 128
#define BN 128
#define BK 16

__global__ __launch_bounds__(256, 2)
void gemm_sims(const float* __restrict__ A, const float* __restrict__ B,
               const float* __restrict__ scale, float* __restrict__ C,
               int M, int N, int K)
{
    __shared__ __align__(16) float As[2][BK][BM];
    __shared__ __align__(16) float Bs[2][BK][BN];

    const int t   = threadIdx.x;
    const int tx  = t & 15;            // 16 thread cols, TN=8
    const int ty  = t >> 4;            // 16 thread rows, TM=8
    const int m0  = blockIdx.y * BM;
    const int n0  = blockIdx.x * BN;

    // global load mapping: 128 rows x 4 k-segments = 512 float4 per operand;
    // each thread loads float4 #t and #(t+256).
    int lr[2], ls[2];
    #pragma unroll
    for (int l = 0; l < 2; ++l) {
        int idx = t + l * 256;
        lr[l] = idx >> 2;              // row 0..127
        ls[l] = (idx & 3) * 4;         // k-offset 0,4,8,12
    }
    const float* gA0 = A + (size_t)(m0 + lr[0]) * K + ls[0];
    const float* gA1 = A + (size_t)(m0 + lr[1]) * K + ls[1];
    const int    br0 = n0 + lr[0];
    const int    br1 = n0 + lr[1];
    const float* gB0 = B + (size_t)br0 * K + ls[0];
    const float* gB1 = B + (size_t)br1 * K + ls[1];
    const bool   bv0 = (br0 < N);
    const bool   bv1 = (br1 < N);

    // accumulators: 8 i-rows x 4 j-pairs, packed f32x2 (lane lo = even j)
    unsigned long long acc2[8][4];
    #pragma unroll
    for (int i = 0; i < 8; ++i)
        #pragma unroll
        for (int jp = 0; jp < 4; ++jp) acc2[i][jp] = 0ull;

    float4 avr[2], bvr[2];
    avr[0] = *(const float4*)(gA0);
    avr[1] = *(const float4*)(gA1);
    bvr[0] = bv0 ? *(const float4*)(gB0) : make_float4(0.f, 0.f, 0.f, 0.f);
    bvr[1] = bv1 ? *(const float4*)(gB1) : make_float4(0.f, 0.f, 0.f, 0.f);

    // store tile 0
    #pragma unroll
    for (int l = 0; l < 2; ++l) {
        As[0][ls[l] + 0][lr[l]] = avr[l].x;
        As[0][ls[l] + 1][lr[l]] = avr[l].y;
        As[0][ls[l] + 2][lr[l]] = avr[l].z;
        As[0][ls[l] + 3][lr[l]] = avr[l].w;
        Bs[0][ls[l] + 0][lr[l]] = bvr[l].x;
        Bs[0][ls[l] + 1][lr[l]] = bvr[l].y;
        Bs[0][ls[l] + 2][lr[l]] = bvr[l].z;
        Bs[0][ls[l] + 3][lr[l]] = bvr[l].w;
    }
    __syncthreads();

    int buf = 0;
    for (int k0 = 0; k0 < K; k0 += BK) {
        const bool more = (k0 + BK) < K;
        if (more) {
            avr[0] = *(const float4*)(gA0 + k0 + BK);
            avr[1] = *(const float4*)(gA1 + k0 + BK);
            bvr[0] = bv0 ? *(const float4*)(gB0 + k0 + BK) : make_float4(0.f, 0.f, 0.f, 0.f);
            bvr[1] = bv1 ? *(const float4*)(gB1 + k0 + BK) : make_float4(0.f, 0.f, 0.f, 0.f);
        }

        #pragma unroll
        for (int kk = 0; kk < BK; ++kk) {
            // a: 8 floats (2x LDS.128), duplicated into f32x2 lanes
            float4 a0 = *(const float4*)&As[buf][kk][ty * 8 + 0];
            float4 a1 = *(const float4*)&As[buf][kk][ty * 8 + 4];
            // b: 4 natural j-pairs (2x LDS.128 viewed as v2.u64)
            ulonglong2 bA = *(const ulonglong2*)&Bs[buf][kk][tx * 8 + 0];
            ulonglong2 bB = *(const ulonglong2*)&Bs[buf][kk][tx * 8 + 4];
            unsigned long long bp[4] = {bA.x, bA.y, bB.x, bB.y};
            unsigned long long ad[8];
            ad[0] = pack2(a0.x, a0.x); ad[1] = pack2(a0.y, a0.y);
            ad[2] = pack2(a0.z, a0.z); ad[3] = pack2(a0.w, a0.w);
            ad[4] = pack2(a1.x, a1.x); ad[5] = pack2(a1.y, a1.y);
            ad[6] = pack2(a1.z, a1.z); ad[7] = pack2(a1.w, a1.w);
            #pragma unroll
            for (int i = 0; i < 8; ++i)
                #pragma unroll
                for (int jp = 0; jp < 4; ++jp)
                    acc2[i][jp] = ffma2(ad[i], bp[jp], acc2[i][jp]);
        }

        if (more) {
            int nb = buf ^ 1;
            #pragma unroll
            for (int l = 0; l < 2; ++l) {
                As[nb][ls[l] + 0][lr[l]] = avr[l].x;
                As[nb][ls[l] + 1][lr[l]] = avr[l].y;
                As[nb][ls[l] + 2][lr[l]] = avr[l].z;
                As[nb][ls[l] + 3][lr[l]] = avr[l].w;
                Bs[nb][ls[l] + 0][lr[l]] = bvr[l].x;
                Bs[nb][ls[l] + 1][lr[l]] = bvr[l].y;
                Bs[nb][ls[l] + 2][lr[l]] = bvr[l].z;
                Bs[nb][ls[l] + 3][lr[l]] = bvr[l].w;
            }
            __syncthreads();
            buf = nb;
        }
    }

    // epilogue: scale by rnorm[n], streaming stores (C consumed once)
    const int nbase = n0 + tx * 8;
    if (nbase < N) {
        float sc[8];
        #pragma unroll
        for (int j = 0; j < 8; ++j) sc[j] = scale[nbase + j];
        #pragma unroll
        for (int i = 0; i < 8; ++i) {
            int m = m0 + ty * 8 + i;
            float r[8];
            #pragma unroll
            for (int jp = 0; jp < 4; ++jp)
                unpack2(acc2[i][jp], r[2 * jp], r[2 * jp + 1]);
            float4 v0 = make_float4(r[0] * sc[0], r[1] * sc[1], r[2] * sc[2], r[3] * sc[3]);
            float4 v1 = make_float4(r[4] * sc[4], r[5] * sc[5], r[6] * sc[6], r[7] * sc[7]);
            __stcs((float4*)(C + (size_t)m * N + nbase), v0);
            __stcs((float4*)(C + (size_t)m * N + nbase + 4), v1);
        }
    }
}

// ---------------- split-K small GEMM: P[kz] = A[M,K-chunk] * B[N,K-chunk]^T ----------------
// BM=64 BN=64 BK=16, 256 threads, 4x4 per-thread tile. Grid (N/64, M/64, SK).
__global__ __launch_bounds__(256)
void gemm64_splitk(const float* __restrict__ A, const float* __restrict__ B,
                   float* __restrict__ P, int M, int N, int K)
{
    __shared__ __align__(16) float As2[16][64];
    __shared__ __align__(16) float Bs2[16][64];

    const int t  = threadIdx.x;
    const int tx = t & 15;             // n, TN=4
    const int ty = t >> 4;             // m, TM=4
    const int m0 = blockIdx.y * 64;
    const int n0 = blockIdx.x * 64;
    const int kz = blockIdx.z;
    const int Kc = K / SK;
    const int kbase = kz * Kc;

    const int row = t >> 2;            // 0..63
    const int ks  = (t & 3) * 4;       // 0,4,8,12
    const float* gA = A + (size_t)(m0 + row) * K + kbase + ks;
    const float* gB = B + (size_t)(n0 + row) * K + kbase + ks;

    float acc[4][4];
    #pragma unroll
    for (int i = 0; i < 4; ++i)
        #pragma unroll
        for (int j = 0; j < 4; ++j) acc[i][j] = 0.f;

    for (int kc = 0; kc < Kc; kc += 16) {
        float4 va = *(const float4*)(gA + kc);
        float4 vb = *(const float4*)(gB + kc);
        __syncthreads();               // protect prior-iteration reads
        As2[ks + 0][row] = va.x; As2[ks + 1][row] = va.y;
        As2[ks + 2][row] = va.z; As2[ks + 3][row] = va.w;
        Bs2[ks + 0][row] = vb.x; Bs2[ks + 1][row] = vb.y;
        Bs2[ks + 2][row] = vb.z; Bs2[ks + 3][row] = vb.w;
        __syncthreads();

        #pragma unroll
        for (int kk = 0; kk < 16; ++kk) {
            float4 a = *(const float4*)&As2[kk][ty * 4];
            float4 b = *(const float4*)&Bs2[kk][tx * 4];
            float av[4] = {a.x, a.y, a.z, a.w};
            float bv[4] = {b.x, b.y, b.z, b.w};
            #pragma unroll
            for (int i = 0; i < 4; ++i)
                #pragma unroll
                for (int j = 0; j < 4; ++j)
                    acc[i][j] = fmaf(av[i], bv[j], acc[i][j]);
        }
    }

    float* Pk = P + (size_t)kz * M * N;
    #pragma unroll
    for (int i = 0; i < 4; ++i) {
        int m = m0 + ty * 4 + i;
        *(float4*)(Pk + (size_t)m * N + n0 + tx * 4) =
            make_float4(acc[i][0], acc[i][1], acc[i][2], acc[i][3]);
    }
}

// ---------------- reduce split-K partials + bias (fixed order -> deterministic) ----------------
__global__ __launch_bounds__(256)
void reduce_bias_kernel(const float* __restrict__ P, const float* __restrict__ bias,
                        float* __restrict__ C, int MN, int N)
{
    int i4 = blockIdx.x * blockDim.x + threadIdx.x;   // float4 index
    if (i4 * 4 >= MN) return;
    const float4* p = (const float4*)P;
    const int stride = MN / 4;
    float4 s0 = p[i4];
    float4 s1 = p[i4 + stride];
    float4 s2 = p[i4 + 2 * stride];
    float4 s3 = p[i4 + 3 * stride];
    int n = (i4 * 4) % N;
    float4 bb = *(const float4*)(bias + n);
    float4 o;
    o.x = s0.x + s1.x + s2.x + s3.x + bb.x;
    o.y = s0.y + s1.y + s2.y + s3.y + bb.y;
    o.z = s0.z + s1.z + s2.z + s3.z + bb.z;
    o.w = s0.w + s1.w + s2.w + s3.w + bb.w;
    ((float4*)C)[i4] = o;
}

// ---------------- LayerNorm + exact GELU (in-place), one block per row ----------------
__global__ __launch_bounds__(256)
void ln_gelu_kernel(float* __restrict__ h, const float* __restrict__ g,
                    const float* __restrict__ b)
{
    __shared__ float red[8];
    int row = blockIdx.x, t = threadIdx.x;
    float4 x = *(const float4*)(h + (size_t)row * DD + t * 4);

    float s = x.x + x.y + x.z + x.w;
    s = block_sum(s, red);
    float mean = s * (1.0f / DD);

    float dx = x.x - mean, dy = x.y - mean, dz = x.z - mean, dw = x.w - mean;
    float ss = dx * dx + dy * dy + dz * dz + dw * dw;
    ss = block_sum(ss, red);
    float rstd = rsqrtf(ss * (1.0f / DD) + 1e-5f);

    float4 gg = *(const float4*)(g + t * 4);
    float4 bb = *(const float4*)(b + t * 4);
    float y0 = dx * rstd * gg.x + bb.x;
    float y1 = dy * rstd * gg.y + bb.y;
    float y2 = dz * rstd * gg.z + bb.z;
    float y3 = dw * rstd * gg.w + bb.w;

    const float inv_sqrt2 = 0.70710678118654752f;
    float4 o;
    o.x = y0 * 0.5f * (1.0f + erff(y0 * inv_sqrt2));
    o.y = y1 * 0.5f * (1.0f + erff(y1 * inv_sqrt2));
    o.z = y2 * 0.5f * (1.0f + erff(y2 * inv_sqrt2));
    o.w = y3 * 0.5f * (1.0f + erff(y3 * inv_sqrt2));
    *(float4*)(h + (size_t)row * DD + t * 4) = o;
}

// ---------------- row L2 normalize: writes scratch + d_out refined region ----------------
__global__ __launch_bounds__(256)
void l2norm_rows_kernel(const float* __restrict__ in, float* __restrict__ out_scratch,
                        float* __restrict__ out_final)
{
    __shared__ float red[8];
    int row = blockIdx.x, t = threadIdx.x;
    float4 x = *(const float4*)(in + (size_t)row * DD + t * 4);
    float ss = x.x * x.x + x.y * x.y + x.z * x.z + x.w * x.w;
    ss = block_sum(ss, red);
    float inv = 1.0f / fmaxf(sqrtf(ss), 1e-12f);
    float4 o = make_float4(x.x * inv, x.y * inv, x.z * inv, x.w * inv);
    *(float4*)(out_scratch + (size_t)row * DD + t * 4) = o;
    *(float4*)(out_final + OFF_REF + (size_t)row * DD + t * 4) = o;
}

// ---------------- memory row inverse norms ----------------
__global__ __launch_bounds__(128)
void rnorm_kernel(const float* __restrict__ mem)
{
    __shared__ float red[4];
    int row = blockIdx.x, t = threadIdx.x;
    const float* p = mem + (size_t)row * DD;
    float4 a = *(const float4*)(p + t * 8);
    float4 c = *(const float4*)(p + t * 8 + 4);
    float ss = a.x*a.x + a.y*a.y + a.z*a.z + a.w*a.w
             + c.x*c.x + c.y*c.y + c.z*c.z + c.w*c.w;
    ss = block_sum(ss, red);
    if (t == 0) g_rnorm[row] = 1.0f / fmaxf(sqrtf(ss), 1e-12f);
}

// ---------------- top-k (k=16) per row, one block per row ----------------
// Tie-break matches jax.lax.top_k: equal values -> smaller index first.
__device__ __forceinline__ bool lexgt(float v2, int i2, float v1, int i1) {
    return (v2 > v1) || (v2 == v1 && i2 < i1);
}

__device__ __forceinline__ void topk_insert(float v, int i, float* val, int* idx) {
    if (lexgt(v, i, val[KTOP - 1], idx[KTOP - 1])) {
        float cv = v; int ci = i;
        #pragma unroll
        for (int j = 0; j < KTOP; ++j) {
            if (lexgt(cv, ci, val[j], idx[j])) {
                float tv = val[j]; int ti = idx[j];
                val[j] = cv; idx[j] = ci;
                cv = tv; ci = ti;
            }
        }
    }
}

__global__ __launch_bounds__(256)
void topk_kernel(const float* __restrict__ sims, float* __restrict__ out)
{
    __shared__ float s_val[256 * KTOP];
    __shared__ int   s_idx[256 * KTOP];
    __shared__ float s_wv[8];
    __shared__ int   s_wi[8];
    __shared__ int   s_fi;

    int row = blockIdx.x, t = threadIdx.x;
    const float4* p4 = (const float4*)(sims + (size_t)row * NMEM);

    float val[KTOP];
    int   idx[KTOP];
    #pragma unroll
    for (int j = 0; j < KTOP; ++j) { val[j] = -INFINITY; idx[j] = 0x7fffffff; }

    const int nq = NMEM / 4;            // 25000
    for (int q = t * 2; q < nq; q += 512) {
        float4 u4 = __ldcs(p4 + q);
        float4 w4 = __ldcs(p4 + q + 1);
        int base = q * 4;
        float e[8] = {u4.x, u4.y, u4.z, u4.w, w4.x, w4.y, w4.z, w4.w};
        #pragma unroll
        for (int s = 0; s < 8; ++s)
            topk_insert(e[s], base + s, val, idx);
    }
    #pragma unroll
    for (int j = 0; j < KTOP; ++j) { s_val[t * KTOP + j] = val[j]; s_idx[t * KTOP + j] = idx[j]; }
    __syncthreads();

    for (int r = 0; r < KTOP; ++r) {
        float bv = -INFINITY; int bi = 0x7fffffff;
        #pragma unroll
        for (int j = 0; j < KTOP; ++j) {
            float v = s_val[t * KTOP + j]; int i = s_idx[t * KTOP + j];
            if (lexgt(v, i, bv, bi)) { bv = v; bi = i; }
        }
        #pragma unroll
        for (int o = 16; o > 0; o >>= 1) {
            float ov = __shfl_down_sync(0xffffffffu, bv, o);
            int   oi = __shfl_down_sync(0xffffffffu, bi, o);
            if (lexgt(ov, oi, bv, bi)) { bv = ov; bi = oi; }
        }
        if ((t & 31) == 0) { s_wv[t >> 5] = bv; s_wi[t >> 5] = bi; }
        __syncthreads();
        if (t == 0) {
            float fv = s_wv[0]; int fi = s_wi[0];
            for (int w = 1; w < 8; ++w)
                if (lexgt(s_wv[w], s_wi[w], fv, fi)) { fv = s_wv[w]; fi = s_wi[w]; }
            s_fi = fi;
            out[OFF_VALS + row * KTOP + r] = fv;
            out[OFF_IDX  + row * KTOP + r] = (float)fi;
            g_tidx[row * KTOP + r] = fi;
        }
        __syncthreads();
        int fi = s_fi;
        #pragma unroll
        for (int j = 0; j < KTOP; ++j)
            if (s_idx[t * KTOP + j] == fi) s_val[t * KTOP + j] = -INFINITY;
        __syncthreads();
    }
}

// ---------------- gather retrieved = mem_n[idx] ----------------
__global__ __launch_bounds__(256)
void gather_kernel(const float* __restrict__ mem, float* __restrict__ out)
{
    int pair = blockIdx.x;            // 0..BQ*KTOP-1
    int idx  = g_tidx[pair];
    float s  = g_rnorm[idx];
    int t = threadIdx.x;
    float4 v = *(const float4*)(mem + (size_t)idx * DD + t * 4);
    float4 o = make_float4(v.x * s, v.y * s, v.z * s, v.w * s);
    *(float4*)(out + OFF_RET + (size_t)pair * DD + t * 4) = o;
}

// ---------------- launch ----------------
extern "C" void kernel_launch(void* const* d_in, const int* in_sizes, int n_in,
                              void* d_out, int out_size)
{
    const float* query = (const float*)d_in[0];
    const float* W1    = (const float*)d_in[1];
    const float* b1    = (const float*)d_in[2];
    const float* ln_g  = (const float*)d_in[3];
    const float* ln_b  = (const float*)d_in[4];
    const float* W2    = (const float*)d_in[5];
    const float* b2    = (const float*)d_in[6];
    const float* mem   = (const float*)d_in[7];
    float* out = (float*)d_out;

    float *p_h, *p_t, *p_ref, *p_sims, *p_rn, *p_part;
    cudaGetSymbolAddress((void**)&p_h,    g_h);
    cudaGetSymbolAddress((void**)&p_t,    g_t);
    cudaGetSymbolAddress((void**)&p_ref,  g_refined);
    cudaGetSymbolAddress((void**)&p_sims, g_sims);
    cudaGetSymbolAddress((void**)&p_rn,   g_rnorm);
    cudaGetSymbolAddress((void**)&p_part, g_part);

    // memory row inverse norms (independent; launch early)
    rnorm_kernel<<<NMEM, 128>>>(mem);

    // h = query @ W1^T + b1  (split-K x4 + reduce)
    gemm64_splitk<<<dim3(DD / 64, BQ / 64, SK), 256>>>(query, W1, p_part, BQ, DD, DD);
    reduce_bias_kernel<<<(BQ * DD / 4 + 255) / 256, 256>>>(p_part, b1, p_h, BQ * DD, DD);
    // LayerNorm + GELU (in place)
    ln_gelu_kernel<<<BQ, 256>>>(p_h, ln_g, ln_b);
    // t = h @ W2^T + b2  (split-K x4 + reduce)
    gemm64_splitk<<<dim3(DD / 64, BQ / 64, SK), 256>>>(p_h, W2, p_part, BQ, DD, DD);
    reduce_bias_kernel<<<(BQ * DD / 4 + 255) / 256, 256>>>(p_part, b2, p_t, BQ * DD, DD);
    // refined = l2norm(t)  (also writes d_out refined region)
    l2norm_rows_kernel<<<BQ, 256>>>(p_t, p_ref, out);

    // sims[b,n] = dot(refined[b], mem[n]) * rnorm[n]  (f32x2 packed FMA)
    gemm_sims<<<dim3((NMEM + BN - 1) / BN, BQ / BM), 256>>>(p_ref, mem, p_rn,
                                                            p_sims, BQ, NMEM, DD);
    // top-16 per row (vals + idx, jax tie-break: smaller index first)
    topk_kernel<<<BQ, 256>>>(p_sims, out);
    // retrieved = mem_n[idx]
    gather_kernel<<<BQ * KTOP, 256>>>(mem, out);
}